// round 9
// baseline (speedup 1.0000x reference)
#include <cuda_runtime.h>
#include <cuda_fp16.h>

#define BATCH 16
#define C_IN  64
#define C_OUT 32
#define V_HI  163842
#define V_LO  40962
#define KNB   7

#define TILES 161                        // 256-vertex tiles: ceil(40962/256)
#define CHUNK_B 4                        // batches per window
#define NWIN (BATCH / CHUNK_B)           // 4 windows

#define WIN_ELEMS (CHUNK_B * C_OUT * V_HI)        // 20,971,776 u32 per window
#define WIN_U4    (WIN_ELEMS / 4)                 // 5,242,944 uint4
#define S_BLOCKS  (CHUNK_B * TILES)               // 644 scatter blocks
#define F_BLOCKS  ((WIN_U4 + 255) / 256)          // 20,481 streaming blocks

// Precomputed neigh table: g_neigh8[v*8+k] = up_neigh[down[v]*7 + k], stride 8.
__device__ int g_neigh8[V_LO * 8];

__global__ void build_neigh_kernel(const int* __restrict__ up_neigh,
                                   const int* __restrict__ down) {
    int v = blockIdx.x * blockDim.x + threadIdx.x;
    if (v >= V_LO) return;
    int dv = down[v];
    const int* src = up_neigh + (long long)dv * KNB;
#pragma unroll
    for (int k = 0; k < KNB; k++) g_neigh8[v * 8 + k] = src[k];
    g_neigh8[v * 8 + 7] = 0;
}

__device__ __forceinline__ float decode_one(unsigned int p) {
    return p ? __half2float(__ushort_as_half((unsigned short)(p & 0xFFFFu))) : 0.0f;
}

// Heterogeneous launch for window k:
//   blocks [0, S_BLOCKS):        fused GEMV + packed-atomicMax scatter into window k
//   blocks [S_BLOCKS, +F_BLOCKS): decode window k-1 (if k>0) and zero window k+1
//                                 (if k<NWIN-1) — disjoint memory, overlaps the
//                                 latency-bound scatter with BW-bound streaming.
// Winner = largest v (reference sequential last-write-wins; collisions only
// within one (b,o) slice).
__global__ __launch_bounds__(256) void mega_kernel(
    const float* __restrict__ x,
    const float* __restrict__ W,
    const float* __restrict__ bias,
    const int*   __restrict__ mpi,
    unsigned int* __restrict__ out32,
    int kwin)
{
    const int tid = threadIdx.x;

    if (blockIdx.x < S_BLOCKS) {
        // ---------------- scatter role (R1-proven body) ----------------
        __shared__ float sW[C_IN][C_OUT + 1];
        __shared__ float sB[C_OUT];

        const int sb = blockIdx.x;
        const int b  = kwin * CHUNK_B + sb / TILES;
        const int v  = (sb % TILES) * 256 + tid;

        for (int i = tid; i < C_IN * C_OUT; i += 256) {
            int o = i / C_IN;
            int c = i % C_IN;
            sW[c][o] = W[i];
        }
        if (tid < C_OUT) sB[tid] = bias[tid];
        __syncthreads();

        if (v >= V_LO) return;

        float h[C_OUT];
#pragma unroll
        for (int o = 0; o < C_OUT; o++) h[o] = sB[o];

        const float* xp = x + ((long long)b * C_IN) * V_LO + v;
#pragma unroll
        for (int c = 0; c < C_IN; c++) {
            float xc = __ldg(xp + (long long)c * V_LO);
#pragma unroll
            for (int o = 0; o < C_OUT; o++) h[o] = fmaf(xc, sW[c][o], h[o]);
        }

        const int4* np = reinterpret_cast<const int4*>(&g_neigh8[v * 8]);
        int4 n0 = np[0];
        int4 n1 = np[1];
        int nb[8] = {n0.x, n0.y, n0.z, n0.w, n1.x, n1.y, n1.z, n1.w};

        const unsigned int vtag = ((unsigned int)(v + 1)) << 16;
        const int* mp = mpi + ((long long)b * C_OUT) * V_LO + v;
        unsigned int* ob = out32 + ((long long)b * C_OUT) * V_HI;

#pragma unroll
        for (int o = 0; o < C_OUT; o++) {
            int k = __ldg(mp + (long long)o * V_LO);   // coalesced
            int u = nb[k];
            unsigned short hb = __half_as_ushort(__float2half_rn(h[o]));
            atomicMax(&ob[(long long)o * V_HI + u], vtag | (unsigned int)hb);
        }
    } else {
        // ---------------- streaming role: decode w(k-1), zero w(k+1) ----------------
        long long i = (long long)(blockIdx.x - S_BLOCKS) * 256 + tid;
        if (i >= WIN_U4) return;
        uint4* out4 = reinterpret_cast<uint4*>(out32);

        if (kwin > 0) {
            long long idx = (long long)(kwin - 1) * WIN_U4 + i;
            uint4 p = out4[idx];
            float4 f;
            f.x = decode_one(p.x);
            f.y = decode_one(p.y);
            f.z = decode_one(p.z);
            f.w = decode_one(p.w);
            reinterpret_cast<float4*>(out4)[idx] = f;
        }
        if (kwin < NWIN - 1) {
            out4[(long long)(kwin + 1) * WIN_U4 + i] = make_uint4(0u, 0u, 0u, 0u);
        }
    }
}

// Epilog decode for the last window.
__global__ __launch_bounds__(256) void finalize_kernel(unsigned int* __restrict__ buf,
                                                       long long n4)
{
    long long i = (long long)blockIdx.x * blockDim.x + threadIdx.x;
    if (i >= n4) return;
    uint4 p = reinterpret_cast<uint4*>(buf)[i];
    float4 f;
    f.x = decode_one(p.x);
    f.y = decode_one(p.y);
    f.z = decode_one(p.z);
    f.w = decode_one(p.w);
    reinterpret_cast<float4*>(buf)[i] = f;
}

extern "C" void kernel_launch(void* const* d_in, const int* in_sizes, int n_in,
                              void* d_out, int out_size) {
    const float* x    = (const float*)d_in[0];   // (16, 64, 40962) f32
    const float* W    = (const float*)d_in[1];   // (32, 64) f32
    const float* bias = (const float*)d_in[2];   // (32,) f32
    const int*   mpi  = (const int*)d_in[3];     // (16, 32, 40962) i32
    const int*   up   = (const int*)d_in[4];     // (163842, 7) i32
    const int*   down = (const int*)d_in[5];     // (40962,) i32

    unsigned int* out32 = (unsigned int*)d_out;  // aliases the f32 output buffer

    // prolog: zero window 0; build neighbor table
    cudaMemsetAsync(out32, 0, (size_t)WIN_ELEMS * sizeof(unsigned int), 0);
    build_neigh_kernel<<<(V_LO + 255) / 256, 256>>>(up, down);

    // 4 heterogeneous launches: scatter(wk) || decode(w(k-1)) || zero(w(k+1))
    for (int k = 0; k < NWIN; k++) {
        mega_kernel<<<S_BLOCKS + F_BLOCKS, 256>>>(x, W, bias, mpi, out32, k);
    }

    // epilog: decode the last window
    finalize_kernel<<<F_BLOCKS, 256>>>(out32 + (long long)(NWIN - 1) * WIN_ELEMS,
                                       (long long)WIN_U4);
}

// round 10
// speedup vs baseline: 1.0083x; 1.0083x over previous
#include <cuda_runtime.h>
#include <cuda_fp16.h>

#define BATCH 16
#define C_IN  64
#define C_OUT 32
#define V_HI  163842
#define V_LO  40962
#define KNB   7

#define TILES 161                        // 256-vertex tiles: ceil(40962/256)
#define CHUNK_B 4                        // batches per window
#define NWIN (BATCH / CHUNK_B)           // 4 windows

#define WIN_ELEMS (CHUNK_B * C_OUT * V_HI)        // 20,971,776 u32 per window
#define WIN_U4    (WIN_ELEMS / 4)                 // 5,242,944 uint4
#define S_BLOCKS  (CHUNK_B * TILES)               // 644 scatter blocks
#define F_BLOCKS  ((WIN_U4 + 255) / 256)          // 20,481 streaming blocks
#define RATIO     33                              // ceil((S+F)/S)
#define MEGA_BLOCKS (S_BLOCKS * RATIO)            // 21,252 (spare streaming bids idle out)

#define NEIGH_BLOCKS ((V_LO + 255) / 256)         // 161

// Precomputed neigh table: g_neigh8[v*8+k] = up_neigh[down[v]*7 + k], stride 8.
__device__ int g_neigh8[V_LO * 8];

__device__ __forceinline__ float decode_one(unsigned int p) {
    return p ? __half2float(__ushort_as_half((unsigned short)(p & 0xFFFFu))) : 0.0f;
}

// Prolog: blocks [0,161) build the neighbor table; the rest zero window 0.
__global__ __launch_bounds__(256) void prolog_kernel(
    const int* __restrict__ up_neigh,
    const int* __restrict__ down,
    unsigned int* __restrict__ out32)
{
    if (blockIdx.x < NEIGH_BLOCKS) {
        int v = blockIdx.x * 256 + threadIdx.x;
        if (v >= V_LO) return;
        int dv = down[v];
        const int* src = up_neigh + (long long)dv * KNB;
#pragma unroll
        for (int k = 0; k < KNB; k++) g_neigh8[v * 8 + k] = src[k];
        g_neigh8[v * 8 + 7] = 0;
    } else {
        long long i = (long long)(blockIdx.x - NEIGH_BLOCKS) * 256 + threadIdx.x;
        if (i >= WIN_U4) return;
        reinterpret_cast<uint4*>(out32)[i] = make_uint4(0u, 0u, 0u, 0u);
    }
}

// Heterogeneous launch for window k, roles INTERLEAVED across blockIdx so both
// resource classes co-reside on the SMs for the whole launch:
//   bid % 33 == 0 (644 blocks): fused GEMV + packed-atomicMax scatter into window k
//   otherwise:                  decode window k-1 (k>0) and zero window k+1 (k<3)
// Disjoint memory; launch boundaries provide all required ordering.
// Winner = largest v (reference sequential last-write-wins; collisions only
// within one (b,o) slice).
__global__ __launch_bounds__(256) void mega_kernel(
    const float* __restrict__ x,
    const float* __restrict__ W,
    const float* __restrict__ bias,
    const int*   __restrict__ mpi,
    unsigned int* __restrict__ out32,
    int kwin)
{
    const int tid = threadIdx.x;
    const unsigned bid = blockIdx.x;

    if (bid % RATIO == 0) {
        // ---------------- scatter role (R1-proven body) ----------------
        const int sb = bid / RATIO;              // 0..643
        if (sb >= S_BLOCKS) return;

        __shared__ float sW[C_IN][C_OUT + 1];
        __shared__ float sB[C_OUT];

        const int b = kwin * CHUNK_B + sb / TILES;
        const int v = (sb % TILES) * 256 + tid;

        for (int i = tid; i < C_IN * C_OUT; i += 256) {
            int o = i / C_IN;
            int c = i % C_IN;
            sW[c][o] = W[i];
        }
        if (tid < C_OUT) sB[tid] = bias[tid];
        __syncthreads();

        if (v >= V_LO) return;

        float h[C_OUT];
#pragma unroll
        for (int o = 0; o < C_OUT; o++) h[o] = sB[o];

        const float* xp = x + ((long long)b * C_IN) * V_LO + v;
#pragma unroll
        for (int c = 0; c < C_IN; c++) {
            float xc = __ldg(xp + (long long)c * V_LO);
#pragma unroll
            for (int o = 0; o < C_OUT; o++) h[o] = fmaf(xc, sW[c][o], h[o]);
        }

        const int4* np = reinterpret_cast<const int4*>(&g_neigh8[v * 8]);
        int4 n0 = np[0];
        int4 n1 = np[1];
        int nb[8] = {n0.x, n0.y, n0.z, n0.w, n1.x, n1.y, n1.z, n1.w};

        const unsigned int vtag = ((unsigned int)(v + 1)) << 16;
        const int* mp = mpi + ((long long)b * C_OUT) * V_LO + v;
        unsigned int* ob = out32 + ((long long)b * C_OUT) * V_HI;

#pragma unroll
        for (int o = 0; o < C_OUT; o++) {
            int k = __ldg(mp + (long long)o * V_LO);   // coalesced
            int u = nb[k];
            unsigned short hb = __half_as_ushort(__float2half_rn(h[o]));
            atomicMax(&ob[(long long)o * V_HI + u], vtag | (unsigned int)hb);
        }
    } else {
        // ---------- streaming role: decode w(k-1), zero w(k+1) ----------
        long long f = (long long)bid - (long long)(bid / RATIO) - 1;  // dense 0..
        long long i = f * 256 + tid;
        if (i >= WIN_U4) return;
        uint4* out4 = reinterpret_cast<uint4*>(out32);

        if (kwin > 0) {
            long long idx = (long long)(kwin - 1) * WIN_U4 + i;
            uint4 p = out4[idx];
            float4 ff;
            ff.x = decode_one(p.x);
            ff.y = decode_one(p.y);
            ff.z = decode_one(p.z);
            ff.w = decode_one(p.w);
            reinterpret_cast<float4*>(out4)[idx] = ff;
        }
        if (kwin < NWIN - 1) {
            out4[(long long)(kwin + 1) * WIN_U4 + i] = make_uint4(0u, 0u, 0u, 0u);
        }
    }
}

// Epilog: decode the last window.
__global__ __launch_bounds__(256) void finalize_kernel(unsigned int* __restrict__ buf,
                                                       long long n4)
{
    long long i = (long long)blockIdx.x * blockDim.x + threadIdx.x;
    if (i >= n4) return;
    uint4 p = reinterpret_cast<uint4*>(buf)[i];
    float4 f;
    f.x = decode_one(p.x);
    f.y = decode_one(p.y);
    f.z = decode_one(p.z);
    f.w = decode_one(p.w);
    reinterpret_cast<float4*>(buf)[i] = f;
}

extern "C" void kernel_launch(void* const* d_in, const int* in_sizes, int n_in,
                              void* d_out, int out_size) {
    const float* x    = (const float*)d_in[0];   // (16, 64, 40962) f32
    const float* W    = (const float*)d_in[1];   // (32, 64) f32
    const float* bias = (const float*)d_in[2];   // (32,) f32
    const int*   mpi  = (const int*)d_in[3];     // (16, 32, 40962) i32
    const int*   up   = (const int*)d_in[4];     // (163842, 7) i32
    const int*   down = (const int*)d_in[5];     // (40962,) i32

    unsigned int* out32 = (unsigned int*)d_out;  // aliases the f32 output buffer

    // prolog: build neigh table || zero window 0
    prolog_kernel<<<NEIGH_BLOCKS + F_BLOCKS, 256>>>(up, down, out32);

    // 4 heterogeneous launches, roles interleaved within each launch
    for (int k = 0; k < NWIN; k++) {
        mega_kernel<<<MEGA_BLOCKS, 256>>>(x, W, bias, mpi, out32, k);
    }

    // epilog: decode the last window
    finalize_kernel<<<F_BLOCKS, 256>>>(out32 + (long long)(NWIN - 1) * WIN_ELEMS,
                                       (long long)WIN_U4);
}

// round 11
// speedup vs baseline: 1.0683x; 1.0595x over previous
#include <cuda_runtime.h>
#include <cuda_fp16.h>

#define BATCH 16
#define C_IN  64
#define C_OUT 32
#define V_HI  163842
#define V_LO  40962
#define KNB   7

#define TILES 161                        // 256-vertex tiles: ceil(40962/256)
#define CHUNK_B 4                        // batches per window
#define NWIN (BATCH / CHUNK_B)           // 4 windows

#define WIN_ELEMS (CHUNK_B * C_OUT * V_HI)        // 20,971,776 u32 per window
#define WIN_U4    (WIN_ELEMS / 4)                 // 5,242,944 uint4
#define S_BLOCKS  (CHUNK_B * TILES)               // 644 scatter blocks
#define RATIO     3
#define MEGA_BLOCKS (S_BLOCKS * RATIO)            // 1932
#define STR_BLOCKS (MEGA_BLOCKS - S_BLOCKS)       // 1288 persistent streaming blocks
#define STR_THREADS ((long long)STR_BLOCKS * 256) // grid-stride width

#define F_BLOCKS  ((WIN_U4 + 255) / 256)          // epilog decode grid

// Precomputed neigh table: g_neigh8[v*8+k] = up_neigh[down[v]*7 + k], stride 8.
__device__ int g_neigh8[V_LO * 8];

__global__ void build_neigh_kernel(const int* __restrict__ up_neigh,
                                   const int* __restrict__ down) {
    int v = blockIdx.x * blockDim.x + threadIdx.x;
    if (v >= V_LO) return;
    int dv = down[v];
    const int* src = up_neigh + (long long)dv * KNB;
#pragma unroll
    for (int k = 0; k < KNB; k++) g_neigh8[v * 8 + k] = src[k];
    g_neigh8[v * 8 + 7] = 0;
}

__device__ __forceinline__ float decode_one(unsigned int p) {
    return p ? __half2float(__ushort_as_half((unsigned short)(p & 0xFFFFu))) : 0.0f;
}

// Heterogeneous launch for window k, both roles PERSISTENT and interleaved:
//   bid % 3 == 0 (644 blocks): fused GEMV + packed-atomicMax scatter into window k
//   else (1288 blocks):        grid-stride streaming loop — decode window k-1
//                              (k>0) and zero window k+1 (k<3).
// Disjoint memory; launch boundaries give all required ordering. Winner =
// largest v (reference sequential last-write-wins; collisions only within one
// (b,o) slice).
__global__ __launch_bounds__(256) void mega_kernel(
    const float* __restrict__ x,
    const float* __restrict__ W,
    const float* __restrict__ bias,
    const int*   __restrict__ mpi,
    unsigned int* __restrict__ out32,
    int kwin)
{
    const int tid = threadIdx.x;
    const unsigned bid = blockIdx.x;

    if (bid % RATIO == 0) {
        // ---------------- scatter role (R1-proven body) ----------------
        const int sb = bid / RATIO;              // 0..643
        __shared__ float sW[C_IN][C_OUT + 1];
        __shared__ float sB[C_OUT];

        const int b = kwin * CHUNK_B + sb / TILES;
        const int v = (sb % TILES) * 256 + tid;

        for (int i = tid; i < C_IN * C_OUT; i += 256) {
            int o = i / C_IN;
            int c = i % C_IN;
            sW[c][o] = W[i];
        }
        if (tid < C_OUT) sB[tid] = bias[tid];
        __syncthreads();

        if (v >= V_LO) return;

        float h[C_OUT];
#pragma unroll
        for (int o = 0; o < C_OUT; o++) h[o] = sB[o];

        const float* xp = x + ((long long)b * C_IN) * V_LO + v;
#pragma unroll
        for (int c = 0; c < C_IN; c++) {
            float xc = __ldg(xp + (long long)c * V_LO);
#pragma unroll
            for (int o = 0; o < C_OUT; o++) h[o] = fmaf(xc, sW[c][o], h[o]);
        }

        const int4* np = reinterpret_cast<const int4*>(&g_neigh8[v * 8]);
        int4 n0 = np[0];
        int4 n1 = np[1];
        int nb[8] = {n0.x, n0.y, n0.z, n0.w, n1.x, n1.y, n1.z, n1.w};

        const unsigned int vtag = ((unsigned int)(v + 1)) << 16;
        const int* mp = mpi + ((long long)b * C_OUT) * V_LO + v;
        unsigned int* ob = out32 + ((long long)b * C_OUT) * V_HI;

#pragma unroll
        for (int o = 0; o < C_OUT; o++) {
            int k = __ldg(mp + (long long)o * V_LO);   // coalesced
            int u = nb[k];
            unsigned short hb = __half_as_ushort(__float2half_rn(h[o]));
            atomicMax(&ob[(long long)o * V_HI + u], vtag | (unsigned int)hb);
        }
    } else {
        // ------- persistent streaming role: decode w(k-1), zero w(k+1) -------
        const long long fblk = (long long)bid - (long long)(bid / RATIO) - 1; // dense
        long long i0 = fblk * 256 + tid;
        uint4* out4 = reinterpret_cast<uint4*>(out32);

        uint4* dec = (kwin > 0)        ? out4 + (long long)(kwin - 1) * WIN_U4 : 0;
        uint4* zer = (kwin < NWIN - 1) ? out4 + (long long)(kwin + 1) * WIN_U4 : 0;
        const uint4 z4 = make_uint4(0u, 0u, 0u, 0u);

        for (long long i = i0; i < WIN_U4; i += STR_THREADS) {
            if (dec) {
                uint4 p = dec[i];
                float4 f;
                f.x = decode_one(p.x);
                f.y = decode_one(p.y);
                f.z = decode_one(p.z);
                f.w = decode_one(p.w);
                reinterpret_cast<float4*>(dec)[i] = f;
            }
            if (zer) zer[i] = z4;
        }
    }
}

// Epilog: decode the last window.
__global__ __launch_bounds__(256) void finalize_kernel(unsigned int* __restrict__ buf,
                                                       long long n4)
{
    long long i = (long long)blockIdx.x * blockDim.x + threadIdx.x;
    if (i >= n4) return;
    uint4 p = reinterpret_cast<uint4*>(buf)[i];
    float4 f;
    f.x = decode_one(p.x);
    f.y = decode_one(p.y);
    f.z = decode_one(p.z);
    f.w = decode_one(p.w);
    reinterpret_cast<float4*>(buf)[i] = f;
}

extern "C" void kernel_launch(void* const* d_in, const int* in_sizes, int n_in,
                              void* d_out, int out_size) {
    const float* x    = (const float*)d_in[0];   // (16, 64, 40962) f32
    const float* W    = (const float*)d_in[1];   // (32, 64) f32
    const float* bias = (const float*)d_in[2];   // (32,) f32
    const int*   mpi  = (const int*)d_in[3];     // (16, 32, 40962) i32
    const int*   up   = (const int*)d_in[4];     // (163842, 7) i32
    const int*   down = (const int*)d_in[5];     // (40962,) i32

    unsigned int* out32 = (unsigned int*)d_out;  // aliases the f32 output buffer

    // prolog: zero window 0 (84MB) + build neigh table
    cudaMemsetAsync(out32, 0, (size_t)WIN_ELEMS * sizeof(unsigned int), 0);
    build_neigh_kernel<<<(V_LO + 255) / 256, 256>>>(up, down);

    // 4 heterogeneous launches: persistent scatter + persistent streaming
    for (int k = 0; k < NWIN; k++) {
        mega_kernel<<<MEGA_BLOCKS, 256>>>(x, W, bias, mpi, out32, k);
    }

    // epilog: decode the last window
    finalize_kernel<<<F_BLOCKS, 256>>>(out32 + (long long)(NWIN - 1) * WIN_ELEMS,
                                       (long long)WIN_U4);
}